// round 1
// baseline (speedup 1.0000x reference)
#include <cuda_runtime.h>

// Problem constants (fixed shapes: x = [64, 512, 512, 3] f32)
#define BATCH 64
#define HW 262144                 // 512*512 pixels per batch
#define TOTAL_PIX (BATCH * HW)    // 16,777,216
#define NBINS 8192
#define CAP 2048                  // candidate capacity per target (expected ~48)
#define K_LO 26214                // floor(0.10 * (HW-1))
#define K_HI 235928               // floor(0.90 * (HW-1))
#define FRAC_LO 0.3f
#define FRAC_HI 0.7f
#define EPSILON 0.01f

// ---- device scratch (static: no runtime allocation) ----
__device__ unsigned int g_hist[BATCH][NBINS];   // 2 MB
__device__ int          g_cnt[BATCH][4];
__device__ int          g_sel_bin[BATCH][4];
__device__ int          g_sel_rank[BATCH][4];
__device__ float        g_cand[BATCH][4][CAP];  // 2 MB
__device__ float        g_stat[BATCH][4];
__device__ float2       g_loinv[BATCH];

// ------------------------------------------------------------------
// k0: zero histogram + counters (graph replays need clean scratch)
// ------------------------------------------------------------------
__global__ void k0_zero() {
    int i = blockIdx.x * blockDim.x + threadIdx.x;
    if (i < BATCH * NBINS) (&g_hist[0][0])[i] = 0u;
    if (i < BATCH * 4)     (&g_cnt[0][0])[i]  = 0;
}

// ------------------------------------------------------------------
// k1: fused channel-mean + per-batch histogram.
//     16 blocks per batch, 1024 threads, 16 pixels/thread.
// ------------------------------------------------------------------
__global__ __launch_bounds__(1024) void k1_mean_hist(const float* __restrict__ x,
                                                     float* __restrict__ xm) {
    __shared__ unsigned int sh[NBINS];   // 32 KB
    const int b     = blockIdx.x >> 4;
    const int chunk = blockIdx.x & 15;

    for (int i = threadIdx.x; i < NBINS; i += 1024) sh[i] = 0u;
    __syncthreads();

    const long base = (long)b * HW + (long)chunk * 16384;
    const float inv3 = 1.0f / 3.0f;

    #pragma unroll
    for (int it = 0; it < 4; it++) {
        const long p = base + it * 4096 + (long)threadIdx.x * 4;  // 4 pixels
        const float4* src = reinterpret_cast<const float4*>(x + p * 3);
        float4 a = src[0];
        float4 c = src[1];
        float4 d = src[2];

        float m0 = (a.x + a.y + a.z) * inv3;
        float m1 = (a.w + c.x + c.y) * inv3;
        float m2 = (c.z + c.w + d.x) * inv3;
        float m3 = (d.y + d.z + d.w) * inv3;

        reinterpret_cast<float4*>(xm)[p >> 2] = make_float4(m0, m1, m2, m3);

        int b0 = min(max((int)(m0 * (float)NBINS), 0), NBINS - 1);
        int b1 = min(max((int)(m1 * (float)NBINS), 0), NBINS - 1);
        int b2 = min(max((int)(m2 * (float)NBINS), 0), NBINS - 1);
        int b3 = min(max((int)(m3 * (float)NBINS), 0), NBINS - 1);
        atomicAdd(&sh[b0], 1u);
        atomicAdd(&sh[b1], 1u);
        atomicAdd(&sh[b2], 1u);
        atomicAdd(&sh[b3], 1u);
    }
    __syncthreads();

    for (int i = threadIdx.x; i < NBINS; i += 1024) {
        unsigned int v = sh[i];
        if (v) atomicAdd(&g_hist[b][i], v);
    }
}

// ------------------------------------------------------------------
// k2: per-batch scan of histogram; locate (bin, rank-in-bin) for the
//     four order statistics. One block per batch, 256 threads x 32 bins.
// ------------------------------------------------------------------
__global__ void k2_scan() {
    const int b   = blockIdx.x;
    const int tid = threadIdx.x;
    __shared__ unsigned int partial[256];
    __shared__ unsigned int prefix[257];

    const int base = tid * 32;
    unsigned int s = 0;
    #pragma unroll
    for (int i = 0; i < 32; i++) s += g_hist[b][base + i];
    partial[tid] = s;
    __syncthreads();

    if (tid == 0) {
        unsigned int acc = 0;
        for (int i = 0; i < 256; i++) { prefix[i] = acc; acc += partial[i]; }
        prefix[256] = acc;
    }
    __syncthreads();

    const unsigned int segBeg = prefix[tid];
    const unsigned int segEnd = prefix[tid + 1];
    const int ranks[4] = {K_LO, K_LO + 1, K_HI, K_HI + 1};

    #pragma unroll
    for (int t = 0; t < 4; t++) {
        const unsigned int r = (unsigned int)ranks[t];
        if (r >= segBeg && r < segEnd) {
            unsigned int c = segBeg;
            for (int i = 0; i < 32; i++) {
                unsigned int h = g_hist[b][base + i];
                if (r < c + h) {
                    g_sel_bin[b][t]  = base + i;
                    g_sel_rank[b][t] = (int)(r - c);
                    break;
                }
                c += h;
            }
        }
    }
}

// ------------------------------------------------------------------
// k3: collect candidate values that fall into the 4 target bins.
// ------------------------------------------------------------------
__global__ __launch_bounds__(256) void k3_collect(const float* __restrict__ xm) {
    const long idx = (long)blockIdx.x * 256 + threadIdx.x;  // float4 index
    const long p   = idx * 4;
    const int  b   = (int)(p >> 18);                         // / 262144

    const int tb0 = g_sel_bin[b][0];
    const int tb1 = g_sel_bin[b][1];
    const int tb2 = g_sel_bin[b][2];
    const int tb3 = g_sel_bin[b][3];

    float4 v = reinterpret_cast<const float4*>(xm)[idx];
    float vals[4] = {v.x, v.y, v.z, v.w};

    #pragma unroll
    for (int j = 0; j < 4; j++) {
        const float f = vals[j];
        const int bin = min(max((int)(f * (float)NBINS), 0), NBINS - 1);
        if (bin == tb0) { int pos = atomicAdd(&g_cnt[b][0], 1); if (pos < CAP) g_cand[b][0][pos] = f; }
        if (bin == tb1) { int pos = atomicAdd(&g_cnt[b][1], 1); if (pos < CAP) g_cand[b][1][pos] = f; }
        if (bin == tb2) { int pos = atomicAdd(&g_cnt[b][2], 1); if (pos < CAP) g_cand[b][2][pos] = f; }
        if (bin == tb3) { int pos = atomicAdd(&g_cnt[b][3], 1); if (pos < CAP) g_cand[b][3][pos] = f; }
    }
}

// ------------------------------------------------------------------
// k4: exact rank-select inside each target bin. Block per (batch, target).
// ------------------------------------------------------------------
__global__ __launch_bounds__(128) void k4_select() {
    const int b = blockIdx.x >> 2;
    const int t = blockIdx.x & 3;
    const int m = min(g_cnt[b][t], CAP);
    const int r = g_sel_rank[b][t];

    __shared__ float sc[CAP];
    for (int i = threadIdx.x; i < m; i += 128) sc[i] = g_cand[b][t][i];
    __syncthreads();

    for (int i = threadIdx.x; i < m; i += 128) {
        const float v = sc[i];
        int cnt = 0;
        for (int j = 0; j < m; j++) {
            const float w = sc[j];
            cnt += (w < v) || (w == v && j < i);
        }
        if (cnt == r) g_stat[b][t] = v;
    }
}

// ------------------------------------------------------------------
// k5: finalize per-batch lo / 1/rng
// ------------------------------------------------------------------
__global__ void k5_final() {
    const int b = threadIdx.x;
    if (b < BATCH) {
        const float lo = g_stat[b][0] + FRAC_LO * (g_stat[b][1] - g_stat[b][0]);
        const float hi = g_stat[b][2] + FRAC_HI * (g_stat[b][3] - g_stat[b][2]);
        const float rng = fmaxf(hi - lo, EPSILON);
        g_loinv[b] = make_float2(lo, 1.0f / rng);
    }
}

// ------------------------------------------------------------------
// k6: normalize in place: clip((xm - lo)/rng, 0, 1)
// ------------------------------------------------------------------
__global__ __launch_bounds__(256) void k6_norm(float* __restrict__ io) {
    const long idx = (long)blockIdx.x * 256 + threadIdx.x;   // float4 index
    const long p   = idx * 4;
    const int  b   = (int)(p >> 18);
    const float2 li = g_loinv[b];

    float4 v = reinterpret_cast<float4*>(io)[idx];
    v.x = __saturatef((v.x - li.x) * li.y);
    v.y = __saturatef((v.y - li.x) * li.y);
    v.z = __saturatef((v.z - li.x) * li.y);
    v.w = __saturatef((v.w - li.x) * li.y);
    reinterpret_cast<float4*>(io)[idx] = v;
}

// ------------------------------------------------------------------
extern "C" void kernel_launch(void* const* d_in, const int* in_sizes, int n_in,
                              void* d_out, int out_size) {
    const float* x  = (const float*)d_in[0];
    float*       out = (float*)d_out;

    k0_zero<<<(BATCH * NBINS + 1023) / 1024, 1024>>>();
    k1_mean_hist<<<BATCH * 16, 1024>>>(x, out);
    k2_scan<<<BATCH, 256>>>();
    k3_collect<<<TOTAL_PIX / 4 / 256, 256>>>(out);
    k4_select<<<BATCH * 4, 128>>>();
    k5_final<<<1, 64>>>();
    k6_norm<<<TOTAL_PIX / 4 / 256, 256>>>(out);
}

// round 2
// speedup vs baseline: 1.0400x; 1.0400x over previous
#include <cuda_runtime.h>

// Problem constants (fixed shapes: x = [64, 512, 512, 3] f32)
#define BATCH 64
#define HW 262144                 // 512*512 pixels per batch
#define TOTAL_PIX (BATCH * HW)    // 16,777,216
#define NBINS 8192
#define CAP 2048                  // candidate capacity per union buffer (expected ~150)
#define K_LO 26214                // floor(0.10 * (HW-1))
#define K_HI 235928               // floor(0.90 * (HW-1))
#define FRAC_LO 0.3f
#define FRAC_HI 0.7f
#define EPSILON 0.01f

// ---- device scratch (static: no runtime allocation; zero-initialized at load,
//      and every kernel that consumes a scratch buffer re-zeroes it for the
//      next graph replay) ----
__device__ unsigned int g_hist[BATCH][NBINS];    // 2 MB
__device__ int          g_cnt[BATCH][2];         // candidate counters (2 union buffers)
__device__ int          g_qbin[BATCH][4];        // bin containing each order stat
__device__ int          g_qcum[BATCH][4];        // cumulative count before that bin
__device__ float        g_cand[BATCH][2][CAP];   // 1 MB candidate values
__device__ float2       g_loinv[BATCH];          // {lo, 1/rng}

// ------------------------------------------------------------------
// k1: fused channel-mean + per-batch histogram.
//     16 blocks per batch, 1024 threads, 16 pixels/thread.
//     x is read with __ldcs (streaming) so the xm we write stays in L2.
// ------------------------------------------------------------------
__global__ __launch_bounds__(1024) void k1_mean_hist(const float* __restrict__ x,
                                                     float* __restrict__ xm) {
    __shared__ unsigned int sh[NBINS];   // 32 KB
    const int b     = blockIdx.x >> 4;
    const int chunk = blockIdx.x & 15;

    for (int i = threadIdx.x; i < NBINS; i += 1024) sh[i] = 0u;
    __syncthreads();

    const long base = (long)b * HW + (long)chunk * 16384;
    const float inv3 = 1.0f / 3.0f;

    #pragma unroll
    for (int it = 0; it < 4; it++) {
        const long p = base + it * 4096 + (long)threadIdx.x * 4;  // 4 pixels
        const float4* src = reinterpret_cast<const float4*>(x + p * 3);
        float4 a = __ldcs(src + 0);
        float4 c = __ldcs(src + 1);
        float4 d = __ldcs(src + 2);

        float m0 = (a.x + a.y + a.z) * inv3;
        float m1 = (a.w + c.x + c.y) * inv3;
        float m2 = (c.z + c.w + d.x) * inv3;
        float m3 = (d.y + d.z + d.w) * inv3;

        reinterpret_cast<float4*>(xm)[p >> 2] = make_float4(m0, m1, m2, m3);

        int b0 = min(max((int)(m0 * (float)NBINS), 0), NBINS - 1);
        int b1 = min(max((int)(m1 * (float)NBINS), 0), NBINS - 1);
        int b2 = min(max((int)(m2 * (float)NBINS), 0), NBINS - 1);
        int b3 = min(max((int)(m3 * (float)NBINS), 0), NBINS - 1);
        atomicAdd(&sh[b0], 1u);
        atomicAdd(&sh[b1], 1u);
        atomicAdd(&sh[b2], 1u);
        atomicAdd(&sh[b3], 1u);
    }
    __syncthreads();

    for (int i = threadIdx.x; i < NBINS; i += 1024) {
        unsigned int v = sh[i];
        if (v) atomicAdd(&g_hist[b][i], v);
    }
}

// ------------------------------------------------------------------
// k2: per-batch scan of histogram; for ranks {K_LO, K_LO+1, K_HI, K_HI+1}
//     find (bin, cumulative-count-before-bin). Zeroes the histogram after
//     consuming it (clean for next graph replay).
//     One block per batch, 256 threads x 32 bins.
// ------------------------------------------------------------------
__global__ void k2_scan() {
    const int b   = blockIdx.x;
    const int tid = threadIdx.x;
    __shared__ unsigned int partial[256];
    __shared__ unsigned int prefix[257];

    const int base = tid * 32;
    unsigned int h[32];
    unsigned int s = 0;
    #pragma unroll
    for (int i = 0; i < 32; i++) { h[i] = g_hist[b][base + i]; s += h[i]; }
    partial[tid] = s;
    __syncthreads();

    if (tid == 0) {
        unsigned int acc = 0;
        for (int i = 0; i < 256; i++) { prefix[i] = acc; acc += partial[i]; }
        prefix[256] = acc;
    }
    __syncthreads();

    const unsigned int segBeg = prefix[tid];
    const unsigned int segEnd = prefix[tid + 1];
    const int ranks[4] = {K_LO, K_LO + 1, K_HI, K_HI + 1};

    #pragma unroll
    for (int t = 0; t < 4; t++) {
        const unsigned int r = (unsigned int)ranks[t];
        if (r >= segBeg && r < segEnd) {
            unsigned int c = segBeg;
            #pragma unroll
            for (int i = 0; i < 32; i++) {
                if (r < c + h[i]) {
                    g_qbin[b][t] = base + i;
                    g_qcum[b][t] = (int)c;
                    break;
                }
                c += h[i];
            }
        }
    }

    // self-clean histogram for next replay (own segment only)
    #pragma unroll
    for (int i = 0; i < 32; i++) g_hist[b][base + i] = 0u;
}

// ------------------------------------------------------------------
// k3: collect candidates in the two union bin windows via cheap float
//     range tests:  (int)(f*NBINS) in [a,b]  <=>  f*NBINS >= a && < b+1.
//     16 floats per thread. xm expected L2-resident.
// ------------------------------------------------------------------
__global__ __launch_bounds__(256) void k3_collect(const float* __restrict__ xm) {
    const long tbase = ((long)blockIdx.x * 256 + threadIdx.x) * 4;  // float4 index
    const long p     = tbase * 4;                                    // first float index
    const int  b     = (int)(p >> 18);                               // / 262144

    const float lo0 = (float)g_qbin[b][0];
    const float lo1 = (float)(g_qbin[b][1] + 1);
    const float hi0 = (float)g_qbin[b][2];
    const float hi1 = (float)(g_qbin[b][3] + 1);

    const float4* src = reinterpret_cast<const float4*>(xm) + tbase;

    #pragma unroll
    for (int q = 0; q < 4; q++) {
        float4 v = src[q];
        float vals[4] = {v.x, v.y, v.z, v.w};
        #pragma unroll
        for (int j = 0; j < 4; j++) {
            const float t = vals[j] * (float)NBINS;
            if (t >= lo0 && t < lo1) {
                int pos = atomicAdd(&g_cnt[b][0], 1);
                if (pos < CAP) g_cand[b][0][pos] = vals[j];
            }
            if (t >= hi0 && t < hi1) {
                int pos = atomicAdd(&g_cnt[b][1], 1);
                if (pos < CAP) g_cand[b][1][pos] = vals[j];
            }
        }
    }
}

// ------------------------------------------------------------------
// k4: exact rank-select among candidates + finalize lo / 1/rng.
//     One block per batch. Self-cleans g_cnt.
// ------------------------------------------------------------------
__global__ __launch_bounds__(256) void k4_select() {
    const int b = blockIdx.x;
    __shared__ float sc[CAP];
    __shared__ float stat[4];

    #pragma unroll
    for (int buf = 0; buf < 2; buf++) {
        const int m  = min(g_cnt[b][buf], CAP);
        const int rA = (buf == 0 ? K_LO : K_HI)     - g_qcum[b][buf * 2];
        const int rB = (buf == 0 ? K_LO + 1 : K_HI + 1) - g_qcum[b][buf * 2];

        for (int i = threadIdx.x; i < m; i += 256) sc[i] = g_cand[b][buf][i];
        __syncthreads();

        for (int i = threadIdx.x; i < m; i += 256) {
            const float v = sc[i];
            int cnt = 0;
            for (int j = 0; j < m; j++) {
                const float w = sc[j];
                cnt += (w < v) || (w == v && j < i);
            }
            if (cnt == rA) stat[buf * 2 + 0] = v;
            if (cnt == rB) stat[buf * 2 + 1] = v;
        }
        __syncthreads();
    }

    if (threadIdx.x == 0) {
        const float lo  = stat[0] + FRAC_LO * (stat[1] - stat[0]);
        const float hi  = stat[2] + FRAC_HI * (stat[3] - stat[2]);
        const float rng = fmaxf(hi - lo, EPSILON);
        g_loinv[b] = make_float2(lo, 1.0f / rng);
        g_cnt[b][0] = 0;
        g_cnt[b][1] = 0;
    }
}

// ------------------------------------------------------------------
// k6: normalize in place: clip((xm - lo)/rng, 0, 1). 16 floats/thread.
// ------------------------------------------------------------------
__global__ __launch_bounds__(256) void k6_norm(float* __restrict__ io) {
    const long tbase = ((long)blockIdx.x * 256 + threadIdx.x) * 4;  // float4 index
    const long p     = tbase * 4;
    const int  b     = (int)(p >> 18);
    const float2 li  = g_loinv[b];

    float4* ptr = reinterpret_cast<float4*>(io) + tbase;

    #pragma unroll
    for (int q = 0; q < 4; q++) {
        float4 v = ptr[q];
        v.x = __saturatef((v.x - li.x) * li.y);
        v.y = __saturatef((v.y - li.x) * li.y);
        v.z = __saturatef((v.z - li.x) * li.y);
        v.w = __saturatef((v.w - li.x) * li.y);
        ptr[q] = v;
    }
}

// ------------------------------------------------------------------
extern "C" void kernel_launch(void* const* d_in, const int* in_sizes, int n_in,
                              void* d_out, int out_size) {
    const float* x   = (const float*)d_in[0];
    float*       out = (float*)d_out;

    k1_mean_hist<<<BATCH * 16, 1024>>>(x, out);
    k2_scan<<<BATCH, 256>>>();
    k3_collect<<<TOTAL_PIX / 16 / 256, 256>>>(out);
    k4_select<<<BATCH, 256>>>();
    k6_norm<<<TOTAL_PIX / 16 / 256, 256>>>(out);
}

// round 4
// speedup vs baseline: 1.0562x; 1.0156x over previous
#include <cuda_runtime.h>

// Problem constants (fixed shapes: x = [64, 512, 512, 3] f32)
#define BATCH 64
#define HW 262144                 // 512*512 pixels per batch
#define TOTAL_PIX (BATCH * HW)    // 16,777,216
#define NBINS 8192
#define CAP 2048                  // candidate capacity per union buffer (expected ~90)
#define K_LO 26214                // floor(0.10 * (HW-1))
#define K_HI 235928               // floor(0.90 * (HW-1))
#define FRAC_LO 0.3f
#define FRAC_HI 0.7f
#define EPSILON 0.01f

#define KB_BLOCKS_PER_BATCH 8
#define KB_THREADS 256
#define F4_PER_BATCH (HW / 4)                              // 65536
#define F4_PER_BLOCK (F4_PER_BATCH / KB_BLOCKS_PER_BATCH)  // 8192

// ---- device scratch (static; zero-initialized at load; every kernel
//      self-cleans what it consumed so graph replays start clean) ----
__device__ unsigned int g_hist[BATCH][NBINS];    // 2 MB
__device__ int          g_tick1[BATCH];          // kA per-batch ticket
__device__ int          g_cnt[BATCH][2];         // candidate counters
__device__ int          g_qbin[BATCH][4];        // bin containing each order stat
__device__ int          g_qcum[BATCH][4];        // cumulative count before that bin
__device__ float        g_cand[BATCH][2][CAP];   // 1 MB candidate values
__device__ float2       g_loinv[BATCH];          // {lo, 1/rng}
__device__ int          g_ready[BATCH];          // loinv published flag
__device__ int          g_tickA[BATCH];          // kB collect ticket
__device__ int          g_tickB[BATCH];          // kB cleanup ticket

// ------------------------------------------------------------------
// kA: fused channel-mean + per-batch histogram + (last block) scan.
//     16 blocks per batch, 1024 threads, 16 pixels/thread.
// ------------------------------------------------------------------
__global__ __launch_bounds__(1024) void kA_mean_hist_scan(const float* __restrict__ x,
                                                          float* __restrict__ xm) {
    __shared__ unsigned int sh[NBINS];   // 32 KB
    const int b     = blockIdx.x >> 4;
    const int chunk = blockIdx.x & 15;
    const int tid   = threadIdx.x;

    for (int i = tid; i < NBINS; i += 1024) sh[i] = 0u;
    __syncthreads();

    const long base = (long)b * HW + (long)chunk * 16384;
    const float inv3 = 1.0f / 3.0f;

    #pragma unroll
    for (int it = 0; it < 4; it++) {
        const long p = base + it * 4096 + (long)tid * 4;  // 4 pixels
        const float4* src = reinterpret_cast<const float4*>(x + p * 3);
        float4 a = __ldcs(src + 0);
        float4 c = __ldcs(src + 1);
        float4 d = __ldcs(src + 2);

        float m0 = (a.x + a.y + a.z) * inv3;
        float m1 = (a.w + c.x + c.y) * inv3;
        float m2 = (c.z + c.w + d.x) * inv3;
        float m3 = (d.y + d.z + d.w) * inv3;

        reinterpret_cast<float4*>(xm)[p >> 2] = make_float4(m0, m1, m2, m3);

        int b0 = min(max((int)(m0 * (float)NBINS), 0), NBINS - 1);
        int b1 = min(max((int)(m1 * (float)NBINS), 0), NBINS - 1);
        int b2 = min(max((int)(m2 * (float)NBINS), 0), NBINS - 1);
        int b3 = min(max((int)(m3 * (float)NBINS), 0), NBINS - 1);
        atomicAdd(&sh[b0], 1u);
        atomicAdd(&sh[b1], 1u);
        atomicAdd(&sh[b2], 1u);
        atomicAdd(&sh[b3], 1u);
    }
    __syncthreads();

    for (int i = tid; i < NBINS; i += 1024) {
        unsigned int v = sh[i];
        if (v) atomicAdd(&g_hist[b][i], v);
    }

    // ---- last-block-done: the 16th block to finish scans this batch ----
    __threadfence();   // release: publish our histogram contributions
    __shared__ int isLast;
    if (tid == 0) isLast = (atomicAdd(&g_tick1[b], 1) == 15);
    __syncthreads();
    if (!isLast) return;
    __threadfence();   // acquire: make other blocks' contributions visible

    // scan 8192 bins with 1024 threads (8 bins each); read via L2 (__ldcg)
    const int lane = tid & 31;
    const int wid  = tid >> 5;
    unsigned int h[8];
    unsigned int s = 0;
    #pragma unroll
    for (int i = 0; i < 8; i++) {
        h[i] = __ldcg(&g_hist[b][tid * 8 + i]);
        s += h[i];
    }

    // warp inclusive scan of s
    unsigned int incl = s;
    #pragma unroll
    for (int o = 1; o < 32; o <<= 1) {
        unsigned int n = __shfl_up_sync(0xffffffffu, incl, o);
        if (lane >= o) incl += n;
    }
    __shared__ unsigned int warpSum[32];
    __shared__ unsigned int warpPre[32];
    if (lane == 31) warpSum[wid] = incl;
    __syncthreads();
    if (wid == 0) {
        unsigned int v = warpSum[lane];
        unsigned int iv = v;
        #pragma unroll
        for (int o = 1; o < 32; o <<= 1) {
            unsigned int n = __shfl_up_sync(0xffffffffu, iv, o);
            if (lane >= o) iv += n;
        }
        warpPre[lane] = iv - v;   // exclusive
    }
    __syncthreads();

    const unsigned int segBeg = warpPre[wid] + incl - s;   // exclusive prefix
    const unsigned int segEnd = segBeg + s;
    const int ranks[4] = {K_LO, K_LO + 1, K_HI, K_HI + 1};

    #pragma unroll
    for (int t = 0; t < 4; t++) {
        const unsigned int r = (unsigned int)ranks[t];
        if (r >= segBeg && r < segEnd) {
            unsigned int c = segBeg;
            #pragma unroll
            for (int i = 0; i < 8; i++) {
                if (r < c + h[i]) {
                    g_qbin[b][t] = tid * 8 + i;
                    g_qcum[b][t] = (int)c;
                    break;
                }
                c += h[i];
            }
        }
    }

    // self-clean for next replay
    #pragma unroll
    for (int i = 0; i < 8; i++) g_hist[b][tid * 8 + i] = 0u;
    if (tid == 0) g_tick1[b] = 0;
}

// ------------------------------------------------------------------
// kB: persistent fused collect -> select -> normalize.
//     512 blocks (8 per batch), 256 threads, fully co-resident, so the
//     per-batch spin on g_ready is deadlock-free.
// ------------------------------------------------------------------
__global__ __launch_bounds__(KB_THREADS) void kB_collect_select_norm(float* __restrict__ io) {
    const int b   = blockIdx.x >> 3;
    const int blk = blockIdx.x & (KB_BLOCKS_PER_BATCH - 1);
    const int tid = threadIdx.x;

    __shared__ float sc[CAP];
    __shared__ float stat[4];
    __shared__ float2 sh_li;
    __shared__ int   isLast;

    const float lo0 = (float)g_qbin[b][0];
    const float lo1 = (float)(g_qbin[b][1] + 1);
    const float hi0 = (float)g_qbin[b][2];
    const float hi1 = (float)(g_qbin[b][3] + 1);

    float4* dat = reinterpret_cast<float4*>(io) + (long)b * F4_PER_BATCH + (long)blk * F4_PER_BLOCK;

    // ---- phase 1: collect candidates ----
    for (int i = tid; i < F4_PER_BLOCK; i += KB_THREADS) {
        float4 v = dat[i];
        float vals[4] = {v.x, v.y, v.z, v.w};
        #pragma unroll
        for (int j = 0; j < 4; j++) {
            const float t = vals[j] * (float)NBINS;
            if (t >= lo0 && t < lo1) {
                int pos = atomicAdd(&g_cnt[b][0], 1);
                if (pos < CAP) g_cand[b][0][pos] = vals[j];
            }
            if (t >= hi0 && t < hi1) {
                int pos = atomicAdd(&g_cnt[b][1], 1);
                if (pos < CAP) g_cand[b][1][pos] = vals[j];
            }
        }
    }

    __threadfence();   // release: publish our candidate writes
    if (tid == 0) isLast = (atomicAdd(&g_tickA[b], 1) == KB_BLOCKS_PER_BATCH - 1);
    __syncthreads();

    // ---- phase 2: last block per batch does exact rank-select ----
    if (isLast) {
        __threadfence();   // acquire: see other blocks' candidate writes

        #pragma unroll
        for (int buf = 0; buf < 2; buf++) {
            const int m  = min(__ldcg(&g_cnt[b][buf]), CAP);
            const int rA = (buf == 0 ? K_LO : K_HI)         - g_qcum[b][buf * 2];
            const int rB = (buf == 0 ? K_LO + 1 : K_HI + 1) - g_qcum[b][buf * 2];

            for (int i = tid; i < m; i += KB_THREADS) sc[i] = __ldcg(&g_cand[b][buf][i]);
            __syncthreads();
            for (int i = tid; i < m; i += KB_THREADS) {
                const float v = sc[i];
                int cnt = 0;
                for (int j = 0; j < m; j++) {
                    const float w = sc[j];
                    cnt += (w < v) || (w == v && j < i);
                }
                if (cnt == rA) stat[buf * 2 + 0] = v;
                if (cnt == rB) stat[buf * 2 + 1] = v;
            }
            __syncthreads();
        }
        if (tid == 0) {
            const float lo  = stat[0] + FRAC_LO * (stat[1] - stat[0]);
            const float hi  = stat[2] + FRAC_HI * (stat[3] - stat[2]);
            const float rng = fmaxf(hi - lo, EPSILON);
            g_loinv[b] = make_float2(lo, 1.0f / rng);
            __threadfence();   // release loinv before flag
            ((volatile int*)g_ready)[b] = 1;
        }
    }

    // ---- wait for loinv (per-batch, overlapped across batches) ----
    if (tid == 0) {
        while (((volatile int*)g_ready)[b] == 0) __nanosleep(64);
        __threadfence();   // acquire
        sh_li = __ldcg(&g_loinv[b]);
    }
    __syncthreads();
    const float2 li = sh_li;

    // ---- phase 3: normalize (data L2-hot from phase 1) ----
    for (int i = tid; i < F4_PER_BLOCK; i += KB_THREADS) {
        float4 v = dat[i];
        v.x = __saturatef((v.x - li.x) * li.y);
        v.y = __saturatef((v.y - li.x) * li.y);
        v.z = __saturatef((v.z - li.x) * li.y);
        v.w = __saturatef((v.w - li.x) * li.y);
        dat[i] = v;
    }

    // ---- cleanup ticket: last block resets all per-batch state ----
    __threadfence();
    if (tid == 0) {
        int t = atomicAdd(&g_tickB[b], 1);
        if (t == KB_BLOCKS_PER_BATCH - 1) {
            g_ready[b]  = 0;
            g_cnt[b][0] = 0;
            g_cnt[b][1] = 0;
            g_tickA[b]  = 0;
            g_tickB[b]  = 0;
        }
    }
}

// ------------------------------------------------------------------
extern "C" void kernel_launch(void* const* d_in, const int* in_sizes, int n_in,
                              void* d_out, int out_size) {
    const float* x   = (const float*)d_in[0];
    float*       out = (float*)d_out;

    kA_mean_hist_scan<<<BATCH * 16, 1024>>>(x, out);
    kB_collect_select_norm<<<BATCH * KB_BLOCKS_PER_BATCH, KB_THREADS>>>(out);
}